// round 4
// baseline (speedup 1.0000x reference)
#include <cuda_runtime.h>
#include <cuda_fp16.h>
#include <cuda_bf16.h>

// Problem constants
#define BB 8
#define CC 4
#define DD 128
#define HH 128
#define WW 128
#define FDIM 512
#define VOL (DD*HH*WW)          // 2097152 = 1<<21

// Per-batch affine coefficients: integer (w,h,d) -> (ix,iy,iz)
// [0..3]=ix: A0*w+A1*h+A2*d+A3   [4..6]=iy: A4*h+A5*d+A6 (pad 7)
// [8..11]=iz: A8*w+A9*h+A10*d+A11
__device__ float g_A[BB * 12];

// Scratch: per voxel slot = {c0..c3 @ x, c0..c3 @ x+1} as 8 fp16 = 16 B.
__device__ uint4 g_scr[(long)BB * VOL];

static __device__ __forceinline__ unsigned pack2(float a, float b) {
    __half2 h = __floats2half2_rn(a, b);
    return *reinterpret_cast<unsigned*>(&h);
}

// ---------------------------------------------------------------------------
// Kernel 1: prep. Block 0 computes per-batch affine coefficients
// (warp-per-batch shuffle reduction of the GEMV). All blocks transpose
// [B,C,D,H,W] fp32 into the fp16 x-pair channels-last scratch.
// ---------------------------------------------------------------------------
__global__ void __launch_bounds__(256)
prep_kernel(const float* __restrict__ x,
            const float* __restrict__ im_feat,
            const float* __restrict__ pos_w,
            const float* __restrict__ pos_b) {
    if (blockIdx.x == 0) {
        const int wid = threadIdx.x >> 5;
        const int lane = threadIdx.x & 31;
        if (wid < BB) {
            float pm = 0.f, pr = 0.f;
            for (int j = lane; j < FDIM; j += 32) {
                float f = im_feat[wid * FDIM + j];
                pm = fmaf(f, pos_w[j], pm);
                pr = fmaf(f, pos_w[FDIM + j], pr);
            }
            #pragma unroll
            for (int s = 16; s; s >>= 1) {
                pm += __shfl_xor_sync(0xffffffffu, pm, s);
                pr += __shfl_xor_sync(0xffffffffu, pr, s);
            }
            if (lane == 0) {
                float mu  = pm + pos_b[0];
                float rho = pr + pos_b[1];
                float cm = cosf(mu),  sm = sinf(mu);
                float cr = cosf(rho), sr = sinf(rho);
                // R = [cm, sm*sr, -sm*cr; 0, cr, sr; sm, -cm*sr, cm*cr]
                const float SC = 128.0f / 127.0f;   // 64 * (2/127)
                float* A = &g_A[wid * 12];
                float r0 = cm, r1 = sm * sr, r2 = -sm * cr;
                float r4 = cr, r5 = sr;
                float r6 = sm, r7 = -cm * sr, r8 = cm * cr;
                A[0] = r0 * SC;  A[1] = r1 * SC;  A[2] = r2 * SC;
                A[3] = 64.0f * (1.0f - (r0 + r1 + r2)) - 0.5f;
                A[4] = r4 * SC;  A[5] = r5 * SC;
                A[6] = 64.0f * (1.0f - (r4 + r5)) - 0.5f;
                A[7] = 0.0f;
                A[8] = r6 * SC;  A[9] = r7 * SC;  A[10] = r8 * SC;
                A[11] = 64.0f * (1.0f - (r6 + r7 + r8)) - 0.5f;
            }
        }
    }

    const long t = (long)blockIdx.x * 256 + threadIdx.x;  // < B*VOL/4
    const long s4 = t << 2;                               // first voxel (global)
    const long b = s4 >> 21;
    const long s = s4 & (VOL - 1);
    const float* base = x + (b << 23);                    // b*C*VOL

    float4 v0 = *(const float4*)(base + s);
    float4 v1 = *(const float4*)(base + VOL + s);
    float4 v2 = *(const float4*)(base + 2L * VOL + s);
    float4 v3 = *(const float4*)(base + 3L * VOL + s);
    const long sn = (s + 4 < VOL) ? (s + 4) : (VOL - 1);  // clamp: value unused (weight 0)
    float a0[5] = {v0.x, v0.y, v0.z, v0.w, base[sn]};
    float a1[5] = {v1.x, v1.y, v1.z, v1.w, base[VOL + sn]};
    float a2[5] = {v2.x, v2.y, v2.z, v2.w, base[2L * VOL + sn]};
    float a3[5] = {v3.x, v3.y, v3.z, v3.w, base[3L * VOL + sn]};

    uint4* dst = g_scr + s4;
    #pragma unroll
    for (int j = 0; j < 4; ++j) {
        uint4 slot;
        slot.x = pack2(a0[j],     a1[j]);
        slot.y = pack2(a2[j],     a3[j]);
        slot.z = pack2(a0[j + 1], a1[j + 1]);
        slot.w = pack2(a2[j + 1], a3[j + 1]);
        dst[j] = slot;
    }
}

// ---------------------------------------------------------------------------
// Kernel 2: rotated trilinear grid_sample. 4 LDG.128 per voxel.
// Affine index math + warp-uniform interior fast path (no clamps/selects).
// grid = (VOL/256, B), block 256.
// ---------------------------------------------------------------------------
__global__ void __launch_bounds__(256)
sample_kernel(float* __restrict__ out) {
    const int b = blockIdx.y;

    __shared__ float A[12];
    if (threadIdx.x < 12) A[threadIdx.x] = g_A[b * 12 + threadIdx.x];
    __syncthreads();

    const unsigned tid = blockIdx.x * 256 + threadIdx.x;   // < VOL
    const int w = tid & (WW - 1);
    const int h = (tid >> 7) & (HH - 1);
    const int d = tid >> 14;
    const float fw = (float)w, fh = (float)h, fd = (float)d;

    const float ix = fmaf(A[0], fw, fmaf(A[1], fh, fmaf(A[2],  fd, A[3])));
    const float iy =               fmaf(A[4], fh, fmaf(A[5],  fd, A[6]));
    const float iz = fmaf(A[8], fw, fmaf(A[9], fh, fmaf(A[10], fd, A[11])));

    const float fxf = floorf(ix), fyf = floorf(iy), fzf = floorf(iz);
    const int ix0 = (int)fxf, iy0 = (int)fyf, iz0 = (int)fzf;
    const float fx = ix - fxf, fy = iy - fyf, fz = iz - fzf;

    float wAv, wBv, wy0, wy1, wz0, wz1;
    int xs, y0c, y1c, z0c, z1c;

    const bool interior = (ix0 >= 0) & (ix0 < WW - 1) &
                          (iy0 >= 0) & (iy0 < HH - 1) &
                          (iz0 >= 0) & (iz0 < DD - 1);

    if (__all_sync(0xffffffffu, interior)) {
        // fast path: no clamps, no zero-selects
        wAv = 1.0f - fx; wBv = fx;
        wy0 = 1.0f - fy; wy1 = fy;
        wz0 = 1.0f - fz; wz1 = fz;
        xs = ix0; y0c = iy0; y1c = iy0 + 1; z0c = iz0; z1c = iz0 + 1;
    } else {
        const int x1 = ix0 + 1, y1 = iy0 + 1, z1 = iz0 + 1;
        const float wx0 = (ix0 >= 0 && ix0 < WW) ? (1.0f - fx) : 0.0f;
        const float wx1 = (x1  >= 0 && x1  < WW) ? fx          : 0.0f;
        wy0 = (iy0 >= 0 && iy0 < HH) ? (1.0f - fy) : 0.0f;
        wy1 = (y1  >= 0 && y1  < HH) ? fy          : 0.0f;
        wz0 = (iz0 >= 0 && iz0 < DD) ? (1.0f - fz) : 0.0f;
        wz1 = (z1  >= 0 && z1  < DD) ? fz          : 0.0f;
        xs  = min(max(ix0, 0), WW - 1);
        wAv = (ix0 >= 0) ? wx0 : wx1;   // weight for slot's first voxel
        wBv = (ix0 >= 0) ? wx1 : 0.0f;  // weight for slot's second voxel
        y0c = min(max(iy0, 0), HH - 1);
        y1c = min(max(y1,  0), HH - 1);
        z0c = min(max(iz0, 0), DD - 1);
        z1c = min(max(z1,  0), DD - 1);
    }

    const int zb0 = z0c * (HH * WW), zb1 = z1c * (HH * WW);
    const int yb0 = y0c * WW,        yb1 = y1c * WW;

    const int o00 = zb0 + yb0 + xs;
    const int o01 = zb0 + yb1 + xs;
    const int o10 = zb1 + yb0 + xs;
    const int o11 = zb1 + yb1 + xs;

    const float c00 = wz0 * wy0;
    const float c01 = wz0 * wy1;
    const float c10 = wz1 * wy0;
    const float c11 = wz1 * wy1;

    const uint4* p = g_scr + ((size_t)b << 21);

    const uint4 g00 = __ldg(p + o00);
    const uint4 g01 = __ldg(p + o01);
    const uint4 g10 = __ldg(p + o10);
    const uint4 g11 = __ldg(p + o11);

    float acc0 = 0.f, acc1 = 0.f, acc2 = 0.f, acc3 = 0.f;

    #define ACC_CORNER(g, cw)                                                   \
    {                                                                           \
        float2 lo01 = __half22float2(*reinterpret_cast<const __half2*>(&g.x));  \
        float2 lo23 = __half22float2(*reinterpret_cast<const __half2*>(&g.y));  \
        float2 hi01 = __half22float2(*reinterpret_cast<const __half2*>(&g.z));  \
        float2 hi23 = __half22float2(*reinterpret_cast<const __half2*>(&g.w));  \
        acc0 = fmaf(cw, fmaf(wAv, lo01.x, wBv * hi01.x), acc0);                 \
        acc1 = fmaf(cw, fmaf(wAv, lo01.y, wBv * hi01.y), acc1);                 \
        acc2 = fmaf(cw, fmaf(wAv, lo23.x, wBv * hi23.x), acc2);                 \
        acc3 = fmaf(cw, fmaf(wAv, lo23.y, wBv * hi23.y), acc3);                 \
    }

    ACC_CORNER(g00, c00)
    ACC_CORNER(g01, c01)
    ACC_CORNER(g10, c10)
    ACC_CORNER(g11, c11)

    const unsigned base = ((unsigned)b << 23) + tid;   // b*C*VOL + tid
    out[base]              = acc0;
    out[base + (1u << 21)] = acc1;
    out[base + (2u << 21)] = acc2;
    out[base + (3u << 21)] = acc3;
}

extern "C" void kernel_launch(void* const* d_in, const int* in_sizes, int n_in,
                              void* d_out, int out_size) {
    const float* x       = (const float*)d_in[0];
    const float* im_feat = (const float*)d_in[1];
    const float* pos_w   = (const float*)d_in[2];
    const float* pos_b   = (const float*)d_in[3];
    float* out = (float*)d_out;

    prep_kernel<<<BB * VOL / 4 / 256, 256>>>(x, im_feat, pos_w, pos_b);
    dim3 grid(VOL / 256, BB);
    sample_kernel<<<grid, 256>>>(out);
}